// round 10
// baseline (speedup 1.0000x reference)
#include <cuda_runtime.h>
#include <math.h>
#include <stdint.h>

#define DIMS    256
#define VOCAB   4096
#define HEADS   2
#define NB      2
#define SEQ     1024
#define DH      128
#define TOKENS  (NB * SEQ)
#define NLAYERS 6

// ---------------- scratch ----------------
__device__ float g_x[TOKENS * DIMS];
__device__ float g_q[NB * HEADS * SEQ * DH];     // [b,h,s,d]
__device__ float g_k[NB * HEADS * SEQ * DH];     // [b,h,s,d]
__device__ float g_vt[NB * HEADS * DH * SEQ];    // [b,h,d,s]
__device__ float g_attn[TOKENS * DIMS];
__device__ float g_a[TOKENS * DIMS];
__device__ float g_h[TOKENS * 2 * DIMS];

// ---------------- helpers ----------------
__device__ __forceinline__ uint32_t f2tf32(float f) {
    uint32_t r;
    asm("cvt.rna.tf32.f32 %0, %1;" : "=r"(r) : "f"(f));
    return r;
}
__device__ __forceinline__ void ldm_x4(uint32_t& r0, uint32_t& r1, uint32_t& r2, uint32_t& r3,
                                       uint32_t addr) {
    asm volatile("ldmatrix.sync.aligned.m8n8.x4.shared.b16 {%0,%1,%2,%3}, [%4];"
                 : "=r"(r0), "=r"(r1), "=r"(r2), "=r"(r3) : "r"(addr));
}
__device__ __forceinline__ void mma_tf32(float* c, const uint32_t* a, const uint32_t* b) {
    asm volatile("mma.sync.aligned.m16n8k8.row.col.f32.tf32.tf32.f32 "
                 "{%0,%1,%2,%3}, {%4,%5,%6,%7}, {%8,%9}, {%0,%1,%2,%3};"
                 : "+f"(c[0]), "+f"(c[1]), "+f"(c[2]), "+f"(c[3])
                 : "r"(a[0]), "r"(a[1]), "r"(a[2]), "r"(a[3]), "r"(b[0]), "r"(b[1]));
}

// ---------------- encoder ----------------
__global__ __launch_bounds__(256) void encode_kernel(
    const int* __restrict__ X, const float* __restrict__ W_enc,
    const float* __restrict__ b_enc, float* __restrict__ xout)
{
    const int t = blockIdx.x;
    const int s = t & (SEQ - 1);
    const int tid = threadIdx.x;

    __shared__ float pos[DIMS];
    {
        const int i = tid;
        const float p = (float)NB - (float)s;
        const int fi = (i < DH) ? i : i - DH;
        const float invf = 1.0f / powf(10000.0f, (float)fi * (1.0f / 128.0f));
        const float ang = p * invf;
        pos[i] = (i < DH) ? sinf(ang) : cosf(ang);
    }
    __syncthreads();

    const int tok = X[t];
    const int warp = tid >> 5, lane = tid & 31;

    #pragma unroll
    for (int o = warp; o < DIMS; o += 8) {
        const float* wrow = W_enc + ((size_t)o * VOCAB + tok) * DIMS;
        const float4* w4 = reinterpret_cast<const float4*>(wrow);
        const float4* p4 = reinterpret_cast<const float4*>(pos);
        float4 wa = w4[lane * 2 + 0], wb = w4[lane * 2 + 1];
        float4 pa = p4[lane * 2 + 0], pb = p4[lane * 2 + 1];
        float acc = wa.x * pa.x + wa.y * pa.y + wa.z * pa.z + wa.w * pa.w
                  + wb.x * pb.x + wb.y * pb.y + wb.z * pb.z + wb.w * pb.w;
        #pragma unroll
        for (int off = 16; off; off >>= 1)
            acc += __shfl_down_sync(0xffffffffu, acc, off);
        if (lane == 0)
            xout[t * DIMS + o] = acc + b_enc[o];
    }
}

// ---------------- tf32 GEMM, 256 thr / 8 warps, 64x64x16 tile ----------------
enum GemmMode {
    MODE_PLAIN = 0,
    MODE_QKV   = 1,   // z=0: Q [b,h,s,d]; z=1: K [b,h,s,d]; z=2: V^T [b,h,d,s]
    MODE_SILU  = 6,
    MODE_RESADD= 7
};

#define BM 64
#define BN 64
#define BK 16
#define PADK 20

template<int MODE>
__global__ __launch_bounds__(256)
void gemm4(const float* __restrict__ A,
           const float* __restrict__ B0, const float* __restrict__ B1, const float* __restrict__ B2,
           float* __restrict__ C0, float* __restrict__ C1, float* __restrict__ C2,
           const float* __restrict__ R,
           int M, int N, int K)
{
    const int z = blockIdx.z;
    const float* B = B0;
    float* C = C0;
    if (MODE == MODE_QKV) {
        B = (z == 0) ? B0 : (z == 1) ? B1 : B2;
        C = (z == 0) ? C0 : (z == 1) ? C1 : C2;
    }

    const int m0 = blockIdx.y * BM;
    const int n0 = blockIdx.x * BN;

    __shared__ uint32_t As[2][BM * PADK];
    __shared__ uint32_t Bs[2][BN * PADK];

    const int tid  = threadIdx.x;
    const int lane = tid & 31;
    const int wid  = tid >> 5;          // 8 warps
    const int wm   = wid >> 1;          // 0..3 -> m offset wm*16
    const int wn   = wid & 1;           // 0..1 -> n offset wn*32

    // A loader: 64 rows x 16 k; each thread one float4
    const int aRow = tid >> 2;
    const int aCol = (tid & 3) * 4;
    const float* gA = A + (size_t)(m0 + aRow) * K + aCol;

    // B loader: [n][k] transposed store; each thread one k-quad for one n
    const int bN = tid & 63;
    const int bQ = tid >> 6;            // 0..3
    const float* gB = B + n0 + bN;

    const int grp = lane >> 3, lr = lane & 7;
    const int aRowOff = (grp & 1) * 8 + lr;
    const int aKoff   = (grp >> 1) * 4;
    const int bRowOff = (grp >> 1) * 8 + lr;
    const int bKoff   = (grp & 1) * 4;

    float acc[4][4];
    #pragma unroll
    for (int j = 0; j < 4; j++)
        #pragma unroll
        for (int r = 0; r < 4; r++) acc[j][r] = 0.f;

    const int nk = K / BK;

    // prologue stage 0
    {
        float4 ra = *reinterpret_cast<const float4*>(gA);
        As[0][aRow * PADK + aCol + 0] = f2tf32(ra.x);
        As[0][aRow * PADK + aCol + 1] = f2tf32(ra.y);
        As[0][aRow * PADK + aCol + 2] = f2tf32(ra.z);
        As[0][aRow * PADK + aCol + 3] = f2tf32(ra.w);
        float r0 = gB[(size_t)(bQ * 4 + 0) * N];
        float r1 = gB[(size_t)(bQ * 4 + 1) * N];
        float r2 = gB[(size_t)(bQ * 4 + 2) * N];
        float r3 = gB[(size_t)(bQ * 4 + 3) * N];
        Bs[0][bN * PADK + bQ * 4 + 0] = f2tf32(r0);
        Bs[0][bN * PADK + bQ * 4 + 1] = f2tf32(r1);
        Bs[0][bN * PADK + bQ * 4 + 2] = f2tf32(r2);
        Bs[0][bN * PADK + bQ * 4 + 3] = f2tf32(r3);
    }
    __syncthreads();

    for (int kt = 0; kt < nk; kt++) {
        const int cur = kt & 1, nxt = cur ^ 1;
        float4 ra;
        float rb[4];
        const bool more = (kt + 1 < nk);
        if (more) {
            ra = *reinterpret_cast<const float4*>(gA + (kt + 1) * BK);
            const float* pB = gB + (size_t)(kt + 1) * BK * N;
            #pragma unroll
            for (int j = 0; j < 4; j++)
                rb[j] = pB[(size_t)(bQ * 4 + j) * N];
        }

        const uint32_t aBase = (uint32_t)__cvta_generic_to_shared(&As[cur][0]);
        const uint32_t bBase = (uint32_t)__cvta_generic_to_shared(&Bs[cur][0]);

        #pragma unroll
        for (int kc = 0; kc < 2; kc++) {
            uint32_t af[4], bf[4][2];
            {
                uint32_t addr = aBase + 4u * ((wm * 16 + aRowOff) * PADK + kc * 8 + aKoff);
                ldm_x4(af[0], af[1], af[2], af[3], addr);
            }
            #pragma unroll
            for (int nt2 = 0; nt2 < 2; nt2++) {
                uint32_t r0, r1, r2, r3;
                uint32_t addr = bBase + 4u * ((wn * 32 + nt2 * 16 + bRowOff) * PADK + kc * 8 + bKoff);
                ldm_x4(r0, r1, r2, r3, addr);
                bf[nt2 * 2 + 0][0] = r0; bf[nt2 * 2 + 0][1] = r1;
                bf[nt2 * 2 + 1][0] = r2; bf[nt2 * 2 + 1][1] = r3;
            }
            #pragma unroll
            for (int nt = 0; nt < 4; nt++)
                mma_tf32(acc[nt], af, bf[nt]);
        }

        if (more) {
            As[nxt][aRow * PADK + aCol + 0] = f2tf32(ra.x);
            As[nxt][aRow * PADK + aCol + 1] = f2tf32(ra.y);
            As[nxt][aRow * PADK + aCol + 2] = f2tf32(ra.z);
            As[nxt][aRow * PADK + aCol + 3] = f2tf32(ra.w);
            #pragma unroll
            for (int j = 0; j < 4; j++)
                Bs[nxt][bN * PADK + bQ * 4 + j] = f2tf32(rb[j]);
        }
        __syncthreads();
    }

    // epilogue
    #pragma unroll
    for (int nt = 0; nt < 4; nt++) {
        const int mrow = m0 + wm * 16 + (lane >> 2);
        const int ncol = n0 + wn * 32 + nt * 8 + 2 * (lane & 3);
        #pragma unroll
        for (int half = 0; half < 2; half++) {
            const int m = mrow + half * 8;
            float v0 = acc[nt][half * 2 + 0], v1 = acc[nt][half * 2 + 1];
            if (MODE == MODE_PLAIN) {
                *reinterpret_cast<float2*>(&C[(size_t)m * N + ncol]) = make_float2(v0, v1);
            } else if (MODE == MODE_SILU) {
                v0 = v0 / (1.f + expf(-v0));
                v1 = v1 / (1.f + expf(-v1));
                *reinterpret_cast<float2*>(&C[(size_t)m * N + ncol]) = make_float2(v0, v1);
            } else if (MODE == MODE_RESADD) {
                float2 r2 = *reinterpret_cast<const float2*>(&R[(size_t)m * N + ncol]);
                *reinterpret_cast<float2*>(&C[(size_t)m * N + ncol]) =
                    make_float2(v0 + r2.x, v1 + r2.y);
            } else if (MODE == MODE_QKV) {
                const int b = m / SEQ, srow = m & (SEQ - 1);
                const int h = ncol / DH, d = ncol & (DH - 1);
                if (z == 2) {  // V^T [b,h,d,s]
                    C[(((size_t)(b * HEADS + h) * DH) + d + 0) * SEQ + srow] = v0;
                    C[(((size_t)(b * HEADS + h) * DH) + d + 1) * SEQ + srow] = v1;
                } else {       // Q/K [b,h,s,d]
                    *reinterpret_cast<float2*>(
                        &C[(((size_t)(b * HEADS + h) * SEQ) + srow) * DH + d]) =
                        make_float2(v0, v1);
                }
            }
        }
    }
}

// ---------------- flash attention ----------------
// grid (32 qtiles, 4 bh), 128 thr / 4 warps. q-tile 32 rows, k-tile 64, dh 128.
#define PADQ 132
#define PADV 68
#define FLASH_SMEM ((32*PADQ + 64*PADQ + 128*PADV + 32*PADV) * 4 + 192 * 4)

__global__ __launch_bounds__(128)
void flash_kernel(const float* __restrict__ Q, const float* __restrict__ K,
                  const float* __restrict__ Vt, float* __restrict__ Oout)
{
    const int qt = 31 - (int)blockIdx.x;   // heavy blocks first
    const int bh = blockIdx.y;
    const int b = bh >> 1, h = bh & 1;
    const int q0 = qt * 32;
    const float scale = 0.08838834764831845f;  // 1/sqrt(128)

    extern __shared__ unsigned char smraw[];
    uint32_t* Qs = (uint32_t*)smraw;          // [32][PADQ]
    uint32_t* Ks = Qs + 32 * PADQ;            // [64][PADQ]
    uint32_t* Vs = Ks + 64 * PADQ;            // [128][PADV]
    uint32_t* Ps = Vs + 128 * PADV;           // [32][PADV]
    float* m_s  = (float*)(Ps + 32 * PADV);   // [32]
    float* l_s  = m_s + 32;                   // [32]
    float* wmax = l_s + 32;                   // [2][32]
    float* wsum = wmax + 64;                  // [2][32]

    const int tid = threadIdx.x, lane = tid & 31, wid = tid >> 5;
    const int mh = wid >> 1;                  // m-half (16 rows)
    const int nh = wid & 1;                   // n-half
    const int grp = lane >> 3, lr = lane & 7;
    const int aRowOff = (grp & 1) * 8 + lr;
    const int aKoff   = (grp >> 1) * 4;
    const int bRowOff = (grp >> 1) * 8 + lr;
    const int bKoff   = (grp & 1) * 4;
    const int r0 = lane >> 2;
    const int cq = 2 * (lane & 3);

    const float* Qg = Q  + (size_t)bh * SEQ * DH;
    const float* Kg = K  + (size_t)bh * SEQ * DH;
    const float* Vg = Vt + (size_t)bh * DH * SEQ;

    // Q tile -> smem (tf32)
    {
        const int r = tid >> 2, part = tid & 3;
        const float* src = Qg + (size_t)(q0 + r) * DH + part * 32;
        uint32_t* dst = Qs + r * PADQ + part * 32;
        #pragma unroll
        for (int j = 0; j < 8; j++) {
            float4 f = reinterpret_cast<const float4*>(src)[j];
            dst[j * 4 + 0] = f2tf32(f.x); dst[j * 4 + 1] = f2tf32(f.y);
            dst[j * 4 + 2] = f2tf32(f.z); dst[j * 4 + 3] = f2tf32(f.w);
        }
    }
    if (tid < 32) { m_s[tid] = -3.0e38f; l_s[tid] = 0.f; }

    float accO[8][4];
    #pragma unroll
    for (int i = 0; i < 8; i++)
        #pragma unroll
        for (int j = 0; j < 4; j++) accO[i][j] = 0.f;

    const int ridx0 = mh * 16 + r0, ridx1 = ridx0 + 8;
    const int nkt = (qt >> 1) + 1;

    for (int kt = 0; kt < nkt; kt++) {
        // K tile 64x128
        {
            const int r = tid >> 1, half = tid & 1;
            const float* src = Kg + (size_t)(kt * 64 + r) * DH + half * 64;
            uint32_t* dst = Ks + r * PADQ + half * 64;
            #pragma unroll
            for (int j = 0; j < 16; j++) {
                float4 f = reinterpret_cast<const float4*>(src)[j];
                dst[j * 4 + 0] = f2tf32(f.x); dst[j * 4 + 1] = f2tf32(f.y);
                dst[j * 4 + 2] = f2tf32(f.z); dst[j * 4 + 3] = f2tf32(f.w);
            }
        }
        // V^T tile 128x64
        {
            const float* src = Vg + (size_t)tid * SEQ + kt * 64;
            uint32_t* dst = Vs + tid * PADV;
            #pragma unroll
            for (int j = 0; j < 16; j++) {
                float4 f = reinterpret_cast<const float4*>(src)[j];
                dst[j * 4 + 0] = f2tf32(f.x); dst[j * 4 + 1] = f2tf32(f.y);
                dst[j * 4 + 2] = f2tf32(f.z); dst[j * 4 + 3] = f2tf32(f.w);
            }
        }
        __syncthreads();

        // S = Q K^T   (warp: rows mh*16+[0,16), cols nh*32+[0,32))
        float accS[4][4];
        #pragma unroll
        for (int i = 0; i < 4; i++)
            #pragma unroll
            for (int j = 0; j < 4; j++) accS[i][j] = 0.f;

        const uint32_t qBase = (uint32_t)__cvta_generic_to_shared(Qs);
        const uint32_t kBase = (uint32_t)__cvta_generic_to_shared(Ks);
        #pragma unroll
        for (int kc = 0; kc < 16; kc++) {
            uint32_t af[4], bf[4][2];
            {
                uint32_t addr = qBase + 4u * ((mh * 16 + aRowOff) * PADQ + kc * 8 + aKoff);
                ldm_x4(af[0], af[1], af[2], af[3], addr);
            }
            #pragma unroll
            for (int nt2 = 0; nt2 < 2; nt2++) {
                uint32_t t0, t1, t2, t3;
                uint32_t addr = kBase + 4u * ((nh * 32 + nt2 * 16 + bRowOff) * PADQ + kc * 8 + bKoff);
                ldm_x4(t0, t1, t2, t3, addr);
                bf[nt2 * 2 + 0][0] = t0; bf[nt2 * 2 + 0][1] = t1;
                bf[nt2 * 2 + 1][0] = t2; bf[nt2 * 2 + 1][1] = t3;
            }
            #pragma unroll
            for (int nt = 0; nt < 4; nt++)
                mma_tf32(accS[nt], af, bf[nt]);
        }

        // scale + causal mask + partial row max
        float pm0 = -3.0e38f, pm1 = -3.0e38f;
        #pragma unroll
        for (int nt = 0; nt < 4; nt++) {
            #pragma unroll
            for (int e = 0; e < 4; e++) {
                const int half = e >> 1, j = e & 1;
                const int col = kt * 64 + nh * 32 + nt * 8 + cq + j;
                const int qr = q0 + mh * 16 + r0 + half * 8;
                float v = accS[nt][e] * scale;
                if (col > qr) v = -1.0e30f;
                accS[nt][e] = v;
                if (half == 0) pm0 = fmaxf(pm0, v); else pm1 = fmaxf(pm1, v);
            }
        }
        pm0 = fmaxf(pm0, __shfl_xor_sync(0xffffffffu, pm0, 1));
        pm0 = fmaxf(pm0, __shfl_xor_sync(0xffffffffu, pm0, 2));
        pm1 = fmaxf(pm1, __shfl_xor_sync(0xffffffffu, pm1, 1));
        pm1 = fmaxf(pm1, __shfl_xor_sync(0xffffffffu, pm1, 2));
        if ((lane & 3) == 0) {
            wmax[nh * 32 + ridx0] = pm0;
            wmax[nh * 32 + ridx1] = pm1;
        }
        __syncthreads();

        const float mold0 = m_s[ridx0], mold1 = m_s[ridx1];
        const float nm0 = fmaxf(mold0, fmaxf(wmax[ridx0], wmax[32 + ridx0]));
        const float nm1 = fmaxf(mold1, fmaxf(wmax[ridx1], wmax[32 + ridx1]));
        const float fac0 = expf(mold0 - nm0);
        const float fac1 = expf(mold1 - nm1);

        // P = exp(S - m), partial sums, stage P to smem
        float ps0 = 0.f, ps1 = 0.f;
        #pragma unroll
        for (int nt = 0; nt < 4; nt++) {
            #pragma unroll
            for (int e = 0; e < 4; e++) {
                const int half = e >> 1, j = e & 1;
                const float p = expf(accS[nt][e] - (half ? nm1 : nm0));
                if (half == 0) ps0 += p; else ps1 += p;
                const int col = nh * 32 + nt * 8 + cq + j;
                Ps[(mh * 16 + r0 + half * 8) * PADV + col] = f2tf32(p);
            }
        }
        ps0 += __shfl_xor_sync(0xffffffffu, ps0, 1);
        ps0 += __shfl_xor_sync(0xffffffffu, ps0, 2);
        ps1 += __shfl_xor_sync(0xffffffffu, ps1, 1);
        ps1 += __shfl_xor_sync(0xffffffffu, ps1, 2);
        if ((lane & 3) == 0) {
            wsum[nh * 32 + ridx0] = ps0;
            wsum[nh * 32 + ridx1] = ps1;
        }
        // rescale O accumulators
        #pragma unroll
        for (int nt = 0; nt < 8; nt++) {
            accO[nt][0] *= fac0; accO[nt][1] *= fac0;
            accO[nt][2] *= fac1; accO[nt][3] *= fac1;
        }
        __syncthreads();

        // stats update (one writer per row)
        if (nh == 0 && (lane & 3) == 0) {
            m_s[ridx0] = nm0;
            l_s[ridx0] = l_s[ridx0] * fac0 + wsum[ridx0] + wsum[32 + ridx0];
            m_s[ridx1] = nm1;
            l_s[ridx1] = l_s[ridx1] * fac1 + wsum[ridx1] + wsum[32 + ridx1];
        }

        // O += P V   (warp: rows mh*16+[0,16), d-cols nh*64+[0,64))
        const uint32_t pBase = (uint32_t)__cvta_generic_to_shared(Ps);
        const uint32_t vBase = (uint32_t)__cvta_generic_to_shared(Vs);
        #pragma unroll
        for (int kc = 0; kc < 8; kc++) {
            uint32_t af[4], bf[8][2];
            {
                uint32_t addr = pBase + 4u * ((mh * 16 + aRowOff) * PADV + kc * 8 + aKoff);
                ldm_x4(af[0], af[1], af[2], af[3], addr);
            }
            #pragma unroll
            for (int nt2 = 0; nt2 < 4; nt2++) {
                uint32_t t0, t1, t2, t3;
                uint32_t addr = vBase + 4u * ((nh * 64 + nt2 * 16 + bRowOff) * PADV + kc * 8 + bKoff);
                ldm_x4(t0, t1, t2, t3, addr);
                bf[nt2 * 2 + 0][0] = t0; bf[nt2 * 2 + 0][1] = t1;
                bf[nt2 * 2 + 1][0] = t2; bf[nt2 * 2 + 1][1] = t3;
            }
            #pragma unroll
            for (int nt = 0; nt < 8; nt++)
                mma_tf32(accO[nt], af, bf[nt]);
        }
        __syncthreads();
    }

    // normalize + write head-concat output
    const float inv0 = 1.f / l_s[ridx0];
    const float inv1 = 1.f / l_s[ridx1];
    #pragma unroll
    for (int nt = 0; nt < 8; nt++) {
        const int d = nh * 64 + nt * 8 + cq;
        const int s0 = q0 + ridx0;
        *reinterpret_cast<float2*>(&Oout[((size_t)(b * SEQ) + s0) * DIMS + h * DH + d]) =
            make_float2(accO[nt][0] * inv0, accO[nt][1] * inv0);
        *reinterpret_cast<float2*>(&Oout[((size_t)(b * SEQ) + s0 + 8) * DIMS + h * DH + d]) =
            make_float2(accO[nt][2] * inv1, accO[nt][3] * inv1);
    }
}

// ---------------- driver ----------------
extern "C" void kernel_launch(void* const* d_in, const int* in_sizes, int n_in,
                              void* d_out, int out_size)
{
    const int*   X     = (const int*)  d_in[0];
    const float* W_enc = (const float*)d_in[1];
    const float* b_enc = (const float*)d_in[2];
    const float* Wq    = (const float*)d_in[3];
    const float* Wk    = (const float*)d_in[4];
    const float* Wv    = (const float*)d_in[5];
    const float* Wo    = (const float*)d_in[6];
    const float* W1    = (const float*)d_in[7];
    const float* W2    = (const float*)d_in[8];
    const float* W_dec = (const float*)d_in[9];
    float* out = (float*)d_out;

    float *x, *q, *k, *vt, *attn, *a, *h;
    cudaGetSymbolAddress((void**)&x,    g_x);
    cudaGetSymbolAddress((void**)&q,    g_q);
    cudaGetSymbolAddress((void**)&k,    g_k);
    cudaGetSymbolAddress((void**)&vt,   g_vt);
    cudaGetSymbolAddress((void**)&attn, g_attn);
    cudaGetSymbolAddress((void**)&a,    g_a);
    cudaGetSymbolAddress((void**)&h,    g_h);

    cudaFuncSetAttribute(flash_kernel, cudaFuncAttributeMaxDynamicSharedMemorySize,
                         FLASH_SMEM);

    encode_kernel<<<TOKENS, 256>>>(X, W_enc, b_enc, x);

    const dim3 gQKV(DIMS / BN, TOKENS / BM, 3);
    const dim3 gSq (DIMS / BN, TOKENS / BM, 1);
    const dim3 gFl (32, NB * HEADS, 1);
    const dim3 gM1 (2 * DIMS / BN, TOKENS / BM, 1);
    const dim3 gDec(VOCAB / BN, TOKENS / BM, 1);

    for (int l = 0; l < NLAYERS; l++) {
        const float* wq = Wq + (size_t)l * DIMS * DIMS;
        const float* wk = Wk + (size_t)l * DIMS * DIMS;
        const float* wv = Wv + (size_t)l * DIMS * DIMS;
        const float* wo = Wo + (size_t)l * DIMS * DIMS;
        const float* w1 = W1 + (size_t)l * DIMS * 2 * DIMS;
        const float* w2 = W2 + (size_t)l * 2 * DIMS * DIMS;

        gemm4<MODE_QKV><<<gQKV, 256>>>(x, wq, wk, wv, q, k, vt, nullptr,
                                       TOKENS, DIMS, DIMS);
        flash_kernel<<<gFl, 128, FLASH_SMEM>>>(q, k, vt, attn);
        gemm4<MODE_PLAIN><<<gSq, 256>>>(attn, wo, nullptr, nullptr, a, nullptr, nullptr, nullptr,
                                        TOKENS, DIMS, DIMS);
        gemm4<MODE_SILU><<<gM1, 256>>>(a, w1, nullptr, nullptr, h, nullptr, nullptr, nullptr,
                                       TOKENS, 2 * DIMS, DIMS);
        gemm4<MODE_RESADD><<<gSq, 256>>>(h, w2, nullptr, nullptr, x, nullptr, nullptr, x,
                                         TOKENS, DIMS, 2 * DIMS);
    }

    gemm4<MODE_PLAIN><<<gDec, 256>>>(x, W_dec, nullptr, nullptr, out, nullptr, nullptr, nullptr,
                                     TOKENS, VOCAB, DIMS);
}